// round 4
// baseline (speedup 1.0000x reference)
#include <cuda_runtime.h>

#define PH   8
#define NN   8
#define KK   64
#define CC   128
#define HH   128
#define WW   128

#define CPB   8                  // channels per block
#define TPB   512

// One block: one (n,k) box, BOTH directions d=0/1, CPB channels.
// Work item = one 16B-aligned plane quad (4 consecutive PHxMW positions) of one
// channel. out0 stored with STG.128; fully-padding quads also store STG.128
// zeros to the d=1 plane (padding is identical in both planes). Valid values
// are scatter-stored (scalar) to the flipped d=1 position, sharing the gather.

__global__ void __launch_bounds__(TPB)
bbp_kernel(const float* __restrict__ x,
           const float* __restrict__ boxes,
           float* __restrict__ feats,
           float* __restrict__ widths,
           int MW)
{
    const int nk  = blockIdx.x;            // n*KK + k
    const int n   = nk >> 6;
    const int cc0 = blockIdx.y * CPB;
    const int tid = threadIdx.x;

    // ---- box parameters (uniform per block) ----
    const float4 b = reinterpret_cast<const float4*>(boxes)[nk];
    const float xmin = b.x, ymin = b.y, xmax = b.z, ymax = b.w;
    const bool valid_box = !(xmin == 0.f && ymin == 0.f && xmax == 0.f && ymax == 0.f);
    const float bw = valid_box ? (xmax - xmin) : 1.f;
    const float bh = valid_box ? (ymax - ymin) : 1.f;
    const bool wide = bw > bh;
    const float ratio = wide ? (bw / bh) : (bh / bw);
    const int   width = valid_box ? (int)ceilf(ratio * (float)PH) : 0;
    const float wf    = (float)(width > 2 ? width : 2);
    const float inv_wf1 = 1.0f / (wf - 1.0f);
    const float inv_ph1 = 1.0f / (float)(PH - 1);

    const int nij      = PH * MW;                 // multiple of 8
    const int quads_pc = nij >> 2;                // quads per channel plane
    const int items    = CPB * quads_pc;          // <= 1024

    // exact floor(pos/MW) for pos < 512 via magic multiply
    const unsigned int magic = (unsigned int)((0x100000000ULL + (unsigned)MW - 1) / (unsigned)MW);

    const float* __restrict__ xbase = x + ((size_t)n * CC + cc0) * (HH * WW);
    float* __restrict__ f0 = feats + (((size_t)nk * 2 + 0) * CC + cc0) * nij;
    float* __restrict__ f1 = feats + (((size_t)nk * 2 + 1) * CC + cc0) * nij;

    for (int it = tid; it < items; it += TPB) {
        const int cl = it / quads_pc;             // quads_pc uniform; cheap enough
        const int qq = it - cl * quads_pc;
        const int p  = qq << 2;                   // plane position of quad start

        const float* __restrict__ xc = xbase + (size_t)cl * (HH * WW);
        float* __restrict__ o0 = f0 + (size_t)cl * nij;
        float* __restrict__ o1 = f1 + (size_t)cl * nij;

        float v[4];
        int   d1[4];
        bool  vv[4];
        bool  anyv = false;

        #pragma unroll
        for (int s = 0; s < 4; ++s) {
            const int pos = p + s;
            const int i = (int)__umulhi((unsigned)pos, magic);
            const int j = pos - i * MW;
            const bool val = (j < width);
            vv[s] = val;
            v[s]  = 0.f;
            d1[s] = pos;
            if (val) {
                anyv = true;
                d1[s] = (PH - 1 - i) * MW + (width - 1 - j);
                float px, py;
                const float fi = (float)i, fj = (float)j;
                if (wide) {
                    px = xmin + fj * bw * inv_wf1;
                    py = ymin + fi * bh * inv_ph1;
                } else {
                    px = xmin + fi * bw * inv_ph1;
                    py = ymin + (wf - fj) * bh * inv_wf1;
                }
                const float ix = px - 0.5f;   // grid normalize/unnormalize cancels
                const float iy = py - 0.5f;
                const float x0f = floorf(ix), y0f = floorf(iy);
                const int x0 = (int)x0f, y0 = (int)y0f;
                const int x1 = x0 + 1,   y1 = y0 + 1;
                const float dx = ix - x0f, dy = iy - y0f;
                const float wx0 = 1.f - dx, wx1 = dx;
                const float wy0 = 1.f - dy, wy1 = dy;
                const bool vx0 = (x0 >= 0) & (x0 < WW);
                const bool vx1 = (x1 >= 0) & (x1 < WW);
                const bool vy0 = (y0 >= 0) & (y0 < HH);
                const bool vy1 = (y1 >= 0) & (y1 < HH);
                const float w00 = (vx0 & vy0) ? wx0 * wy0 : 0.f;
                const float w10 = (vx1 & vy0) ? wx1 * wy0 : 0.f;
                const float w01 = (vx0 & vy1) ? wx0 * wy1 : 0.f;
                const float w11 = (vx1 & vy1) ? wx1 * wy1 : 0.f;
                const int xc0 = min(max(x0, 0), WW - 1);
                const int xc1 = min(max(x1, 0), WW - 1);
                const int yc0 = min(max(y0, 0), HH - 1);
                const int yc1 = min(max(y1, 0), HH - 1);
                v[s] = w00 * __ldg(xc + yc0 * WW + xc0)
                     + w10 * __ldg(xc + yc0 * WW + xc1)
                     + w01 * __ldg(xc + yc1 * WW + xc0)
                     + w11 * __ldg(xc + yc1 * WW + xc1);
            }
        }

        // d=0 plane: aligned vector store
        float4 vq;
        vq.x = v[0]; vq.y = v[1]; vq.z = v[2]; vq.w = v[3];
        __stwt(reinterpret_cast<float4*>(o0 + p), vq);

        // d=1 plane
        if (!anyv) {
            // all padding: identical zero quad at the same aligned position
            __stwt(reinterpret_cast<float4*>(o1 + p), vq);
        } else {
            #pragma unroll
            for (int s = 0; s < 4; ++s)
                __stwt(o1 + d1[s], v[s]);   // flipped scatter (or self-pos zero)
        }
    }

    if (tid == 0 && blockIdx.y == 0) {
        widths[(size_t)nk * 2 + 0] = (float)width;
        widths[(size_t)nk * 2 + 1] = (float)width;
    }
}

extern "C" void kernel_launch(void* const* d_in, const int* in_sizes, int n_in,
                              void* d_out, int out_size)
{
    const float* x     = (const float*)d_in[0];
    const float* boxes = (const float*)d_in[1];
    float* out = (float*)d_out;

    // out = concat(feats (N,K,2,C,PH,MW), widths (N,K,2))
    const long long widths_elems = (long long)NN * KK * 2;               // 1024
    const long long per_mw       = (long long)NN * KK * 2 * CC * PH;     // 1048576
    int MW = (int)(((long long)out_size - widths_elems) / per_mw);
    if (MW < 1) MW = 1;
    if (MW > 64) MW = 64;   // nij <= 512 by construction (ratio < 8)

    float* feats  = out;
    float* widths = out + (size_t)per_mw * MW;

    dim3 grid(NN * KK, CC / CPB);
    bbp_kernel<<<grid, TPB>>>(x, boxes, feats, widths, MW);
}

// round 5
// speedup vs baseline: 1.3584x; 1.3584x over previous
#include <cuda_runtime.h>

#define PH   8
#define NN   8
#define KK   64
#define CC   128
#define HH   128
#define WW   128
#define HW   (HH * WW)

#define CPB   8                  // channels per block
#define TPB   128                // one quad (4 positions) per thread; quads <= 128

// One block: one (n,k) box, BOTH directions d=0/1, CPB channels.
// Thread owns one 16B-aligned quad of the PHxMW plane: 4 bilinear records
// computed ONCE (packed in registers), reused across the channel loop.
// d=0 plane stored with STG.128. d=1 plane is the flip of d=0 within valid
// columns: valid values scatter-stored scalar, all-padding quads stored as
// one vector zero (padding positions coincide in both planes).

__global__ void __launch_bounds__(TPB, 8)
bbp_kernel(const float* __restrict__ x,
           const float* __restrict__ boxes,
           float* __restrict__ feats,
           float* __restrict__ widths,
           int MW)
{
    const int nk  = blockIdx.x;            // n*KK + k
    const int n   = nk >> 6;
    const int cc0 = blockIdx.y * CPB;
    const int tid = threadIdx.x;

    // ---- box parameters (uniform per block) ----
    const float4 b = reinterpret_cast<const float4*>(boxes)[nk];
    const float xmin = b.x, ymin = b.y, xmax = b.z, ymax = b.w;
    const bool valid_box = !(xmin == 0.f && ymin == 0.f && xmax == 0.f && ymax == 0.f);
    const float bwf = valid_box ? (xmax - xmin) : 1.f;
    const float bhf = valid_box ? (ymax - ymin) : 1.f;
    const bool wide = bwf > bhf;
    const float ratio = wide ? (bwf / bhf) : (bhf / bwf);
    const int   width = valid_box ? (int)ceilf(ratio * (float)PH) : 0;
    const float wf    = (float)(width > 2 ? width : 2);
    const float inv_wf1 = 1.0f / (wf - 1.0f);
    const float inv_ph1 = 1.0f / (float)(PH - 1);

    const int nij   = PH * MW;             // multiple of 8
    const int quads = nij >> 2;            // <= 128

    if (tid == 0 && blockIdx.y == 0) {
        widths[(size_t)nk * 2 + 0] = (float)width;
        widths[(size_t)nk * 2 + 1] = (float)width;
    }
    if (tid >= quads) return;

    const int p = tid << 2;                // quad start position in plane

    // exact floor(pos/MW) for pos < 512 via magic multiply
    const unsigned int magic = (unsigned int)((0x100000000ULL + (unsigned)MW - 1) / (unsigned)MW);

    // ---- per-thread records (computed once) ----
    unsigned off_a[4];   // packed: off00 | off10<<16
    unsigned off_b[4];   // packed: off01 | off11<<16
    float4   wt[4];
    int      d1[4];
    unsigned vmask = 0;

    #pragma unroll
    for (int s = 0; s < 4; ++s) {
        const int pos = p + s;
        const int i = (int)__umulhi((unsigned)pos, magic);
        const int j = pos - i * MW;
        off_a[s] = 0; off_b[s] = 0;
        wt[s] = make_float4(0.f, 0.f, 0.f, 0.f);
        d1[s] = pos;
        if (j < width) {
            vmask |= (1u << s);
            d1[s] = (PH - 1 - i) * MW + (width - 1 - j);
            float px, py;
            const float fi = (float)i, fj = (float)j;
            if (wide) {
                px = xmin + fj * bwf * inv_wf1;
                py = ymin + fi * bhf * inv_ph1;
            } else {
                px = xmin + fi * bwf * inv_ph1;
                py = ymin + (wf - fj) * bhf * inv_wf1;
            }
            const float ix = px - 0.5f;    // grid normalize/unnormalize cancels
            const float iy = py - 0.5f;
            const float x0f = floorf(ix), y0f = floorf(iy);
            const int x0 = (int)x0f, y0 = (int)y0f;
            const int x1 = x0 + 1,   y1 = y0 + 1;
            const float dx = ix - x0f, dy = iy - y0f;
            const float wx0 = 1.f - dx, wx1 = dx;
            const float wy0 = 1.f - dy, wy1 = dy;
            const bool vx0 = (x0 >= 0) & (x0 < WW);
            const bool vx1 = (x1 >= 0) & (x1 < WW);
            const bool vy0 = (y0 >= 0) & (y0 < HH);
            const bool vy1 = (y1 >= 0) & (y1 < HH);
            wt[s].x = (vx0 & vy0) ? wx0 * wy0 : 0.f;
            wt[s].y = (vx1 & vy0) ? wx1 * wy0 : 0.f;
            wt[s].z = (vx0 & vy1) ? wx0 * wy1 : 0.f;
            wt[s].w = (vx1 & vy1) ? wx1 * wy1 : 0.f;
            const unsigned xc0 = (unsigned)min(max(x0, 0), WW - 1);
            const unsigned xc1 = (unsigned)min(max(x1, 0), WW - 1);
            const unsigned yc0 = (unsigned)min(max(y0, 0), HH - 1);
            const unsigned yc1 = (unsigned)min(max(y1, 0), HH - 1);
            off_a[s] = (yc0 * WW + xc0) | ((yc0 * WW + xc1) << 16);
            off_b[s] = (yc1 * WW + xc0) | ((yc1 * WW + xc1) << 16);
        }
    }

    // ---- channel loop: records reused, 16 independent gathers per channel ----
    const float* __restrict__ xbase = x + ((size_t)n * CC + cc0) * HW;
    float* __restrict__ f0 = feats + (((size_t)nk * 2 + 0) * CC + cc0) * nij;
    float* __restrict__ f1 = feats + (((size_t)nk * 2 + 1) * CC + cc0) * nij;

    #pragma unroll 2
    for (int c = 0; c < CPB; ++c) {
        const float* __restrict__ xc = xbase + (size_t)c * HW;
        float* __restrict__ o0 = f0 + (size_t)c * nij;
        float* __restrict__ o1 = f1 + (size_t)c * nij;

        float4 vq = make_float4(0.f, 0.f, 0.f, 0.f);
        float* vs = &vq.x;

        if (vmask) {
            #pragma unroll
            for (int s = 0; s < 4; ++s) {
                if (vmask & (1u << s)) {
                    const float g00 = __ldg(xc + (off_a[s] & 0xFFFFu));
                    const float g10 = __ldg(xc + (off_a[s] >> 16));
                    const float g01 = __ldg(xc + (off_b[s] & 0xFFFFu));
                    const float g11 = __ldg(xc + (off_b[s] >> 16));
                    vs[s] = wt[s].x * g00 + wt[s].y * g10
                          + wt[s].z * g01 + wt[s].w * g11;
                }
            }
        }

        __stwt(reinterpret_cast<float4*>(o0 + p), vq);   // d=0: vector

        if (!vmask) {
            __stwt(reinterpret_cast<float4*>(o1 + p), vq);  // all padding: vector zero
        } else {
            #pragma unroll
            for (int s = 0; s < 4; ++s)
                __stwt(o1 + d1[s], vs[s]);   // flipped (or self-pos zero pad)
        }
    }
}

extern "C" void kernel_launch(void* const* d_in, const int* in_sizes, int n_in,
                              void* d_out, int out_size)
{
    const float* x     = (const float*)d_in[0];
    const float* boxes = (const float*)d_in[1];
    float* out = (float*)d_out;

    // out = concat(feats (N,K,2,C,PH,MW), widths (N,K,2))
    const long long widths_elems = (long long)NN * KK * 2;               // 1024
    const long long per_mw       = (long long)NN * KK * 2 * CC * PH;     // 1048576
    int MW = (int)(((long long)out_size - widths_elems) / per_mw);
    if (MW < 1) MW = 1;
    if (MW > 64) MW = 64;   // nij <= 512 by construction (ratio < 8)

    float* feats  = out;
    float* widths = out + (size_t)per_mw * MW;

    dim3 grid(NN * KK, CC / CPB);
    bbp_kernel<<<grid, TPB>>>(x, boxes, feats, widths, MW);
}

// round 6
// speedup vs baseline: 1.5465x; 1.1385x over previous
#include <cuda_runtime.h>

#define PH   8
#define NN   8
#define KK   64
#define CC   128
#define HH   128
#define WW   128
#define HW   (HH * WW)

#define CPB   8                  // channels per block
#define TPB   256                // one pair (2 positions) per thread; pairs <= 256

// One block: one (n,k) box, BOTH directions d=0/1, CPB channels.
// Thread owns one 8B-aligned pair of the PHxMW plane: 2 bilinear records
// computed ONCE, reused across the channel loop (MLP from full unroll).
// d=0 plane stored with STG.64. d=1 plane is the flip within valid columns:
// both-padding pairs -> vector zero at same slot; both-valid pairs with
// adjacent+aligned flipped destinations -> reversed STG.64; else scalars.

__global__ void __launch_bounds__(TPB)
bbp_kernel(const float* __restrict__ x,
           const float* __restrict__ boxes,
           float* __restrict__ feats,
           float* __restrict__ widths,
           int MW)
{
    const int nk  = blockIdx.x;            // n*KK + k
    const int n   = nk >> 6;
    const int cc0 = blockIdx.y * CPB;
    const int tid = threadIdx.x;

    // ---- box parameters (uniform per block) ----
    const float4 b = reinterpret_cast<const float4*>(boxes)[nk];
    const float xmin = b.x, ymin = b.y, xmax = b.z, ymax = b.w;
    const bool valid_box = !(xmin == 0.f && ymin == 0.f && xmax == 0.f && ymax == 0.f);
    const float bwf = valid_box ? (xmax - xmin) : 1.f;
    const float bhf = valid_box ? (ymax - ymin) : 1.f;
    const bool wide = bwf > bhf;
    const float ratio = wide ? (bwf / bhf) : (bhf / bwf);
    const int   width = valid_box ? (int)ceilf(ratio * (float)PH) : 0;
    const float wf    = (float)(width > 2 ? width : 2);
    const float inv_wf1 = 1.0f / (wf - 1.0f);
    const float inv_ph1 = 1.0f / (float)(PH - 1);

    const int nij   = PH * MW;             // multiple of 8
    const int pairs = nij >> 1;            // <= 256

    if (tid == 0 && blockIdx.y == 0) {
        widths[(size_t)nk * 2 + 0] = (float)width;
        widths[(size_t)nk * 2 + 1] = (float)width;
    }
    if (tid >= pairs) return;

    const int p = tid << 1;                // pair start position in plane

    // exact floor(pos/MW) for pos < 512 via magic multiply
    const unsigned int magic = (unsigned int)((0x100000000ULL + (unsigned)MW - 1) / (unsigned)MW);

    // ---- per-thread records (computed once) ----
    unsigned off_a[2];   // packed: off00 | off10<<16
    unsigned off_b[2];   // packed: off01 | off11<<16
    float4   wt[2];
    int      d1[2];
    unsigned vmask = 0;

    #pragma unroll
    for (int s = 0; s < 2; ++s) {
        const int pos = p + s;
        const int i = (int)__umulhi((unsigned)pos, magic);
        const int j = pos - i * MW;
        off_a[s] = 0; off_b[s] = 0;
        wt[s] = make_float4(0.f, 0.f, 0.f, 0.f);
        d1[s] = pos;
        if (j < width) {
            vmask |= (1u << s);
            d1[s] = (PH - 1 - i) * MW + (width - 1 - j);
            float px, py;
            const float fi = (float)i, fj = (float)j;
            if (wide) {
                px = xmin + fj * bwf * inv_wf1;
                py = ymin + fi * bhf * inv_ph1;
            } else {
                px = xmin + fi * bwf * inv_ph1;
                py = ymin + (wf - fj) * bhf * inv_wf1;
            }
            const float ix = px - 0.5f;    // grid normalize/unnormalize cancels
            const float iy = py - 0.5f;
            const float x0f = floorf(ix), y0f = floorf(iy);
            const int x0 = (int)x0f, y0 = (int)y0f;
            const int x1 = x0 + 1,   y1 = y0 + 1;
            const float dx = ix - x0f, dy = iy - y0f;
            const float wx0 = 1.f - dx, wx1 = dx;
            const float wy0 = 1.f - dy, wy1 = dy;
            const bool vx0 = (x0 >= 0) & (x0 < WW);
            const bool vx1 = (x1 >= 0) & (x1 < WW);
            const bool vy0 = (y0 >= 0) & (y0 < HH);
            const bool vy1 = (y1 >= 0) & (y1 < HH);
            wt[s].x = (vx0 & vy0) ? wx0 * wy0 : 0.f;
            wt[s].y = (vx1 & vy0) ? wx1 * wy0 : 0.f;
            wt[s].z = (vx0 & vy1) ? wx0 * wy1 : 0.f;
            wt[s].w = (vx1 & vy1) ? wx1 * wy1 : 0.f;
            const unsigned xc0 = (unsigned)min(max(x0, 0), WW - 1);
            const unsigned xc1 = (unsigned)min(max(x1, 0), WW - 1);
            const unsigned yc0 = (unsigned)min(max(y0, 0), HH - 1);
            const unsigned yc1 = (unsigned)min(max(y1, 0), HH - 1);
            off_a[s] = (yc0 * WW + xc0) | ((yc0 * WW + xc1) << 16);
            off_b[s] = (yc1 * WW + xc0) | ((yc1 * WW + xc1) << 16);
        }
    }

    // d=1 vector-store feasibility: flipped destinations adjacent + 8B aligned
    const bool vec1 = (vmask == 3u) && (d1[1] + 1 == d1[0]) && ((d1[1] & 1) == 0);

    // ---- channel loop: records reused ----
    const float* __restrict__ xbase = x + ((size_t)n * CC + cc0) * HW;
    float* __restrict__ f0 = feats + (((size_t)nk * 2 + 0) * CC + cc0) * nij;
    float* __restrict__ f1 = feats + (((size_t)nk * 2 + 1) * CC + cc0) * nij;

    #pragma unroll
    for (int c = 0; c < CPB; ++c) {
        const float* __restrict__ xc = xbase + (size_t)c * HW;
        float* __restrict__ o0 = f0 + (size_t)c * nij;
        float* __restrict__ o1 = f1 + (size_t)c * nij;

        float v0 = 0.f, v1 = 0.f;
        if (vmask & 1u) {
            v0 = wt[0].x * __ldg(xc + (off_a[0] & 0xFFFFu))
               + wt[0].y * __ldg(xc + (off_a[0] >> 16))
               + wt[0].z * __ldg(xc + (off_b[0] & 0xFFFFu))
               + wt[0].w * __ldg(xc + (off_b[0] >> 16));
        }
        if (vmask & 2u) {
            v1 = wt[1].x * __ldg(xc + (off_a[1] & 0xFFFFu))
               + wt[1].y * __ldg(xc + (off_a[1] >> 16))
               + wt[1].z * __ldg(xc + (off_b[1] & 0xFFFFu))
               + wt[1].w * __ldg(xc + (off_b[1] >> 16));
        }

        __stwt(reinterpret_cast<float2*>(o0 + p), make_float2(v0, v1));  // d=0

        if (vmask == 0u) {
            __stwt(reinterpret_cast<float2*>(o1 + p), make_float2(0.f, 0.f));
        } else if (vec1) {
            __stwt(reinterpret_cast<float2*>(o1 + d1[1]), make_float2(v1, v0));
        } else {
            __stwt(o1 + d1[0], v0);
            __stwt(o1 + d1[1], v1);
        }
    }
}

extern "C" void kernel_launch(void* const* d_in, const int* in_sizes, int n_in,
                              void* d_out, int out_size)
{
    const float* x     = (const float*)d_in[0];
    const float* boxes = (const float*)d_in[1];
    float* out = (float*)d_out;

    // out = concat(feats (N,K,2,C,PH,MW), widths (N,K,2))
    const long long widths_elems = (long long)NN * KK * 2;               // 1024
    const long long per_mw       = (long long)NN * KK * 2 * CC * PH;     // 1048576
    int MW = (int)(((long long)out_size - widths_elems) / per_mw);
    if (MW < 1) MW = 1;
    if (MW > 64) MW = 64;   // nij <= 512 by construction (ratio < 8)

    float* feats  = out;
    float* widths = out + (size_t)per_mw * MW;

    dim3 grid(NN * KK, CC / CPB);
    bbp_kernel<<<grid, TPB>>>(x, boxes, feats, widths, MW);
}